// round 13
// baseline (speedup 1.0000x reference)
#include <cuda_runtime.h>
#include <cuda_fp16.h>
#include <math.h>
#include <stdint.h>

#define SEQ   4096
#define DIM   1024
#define OUTD  2048
#define SCALE 0.03125f   // 1/sqrt(1024)

#define PADH  40                        // 32 halves + 8 pad per smem row (80 B)
#define BBUF  (128 * PADH * 2)          // B tile: 10240 B

// ---------------------------------------------------------------------------
// scratch (__device__ globals; no allocations allowed)
// ---------------------------------------------------------------------------
__device__ __half g_x [(size_t)SEQ * DIM];          // x (fp16)
__device__ __half g_wt[(size_t)3 * DIM * DIM];      // W^T (Q,K,V) (fp16)
__device__ __half g_q [(size_t)SEQ * DIM];
__device__ __half g_k [(size_t)SEQ * DIM];
__device__ __half g_vt[(size_t)DIM * SEQ];          // V^T [d][s]
__device__ __half g_s [(size_t)SEQ * SEQ];          // scaled scores (fp16)
__device__ __half g_p [(size_t)SEQ * SEQ];          // probs (fp16)

// ---------------------------------------------------------------------------
// helpers
// ---------------------------------------------------------------------------
__device__ __forceinline__ uint32_t smem_u32(const void* p) {
    uint32_t a;
    asm("{ .reg .u64 t; cvta.to.shared.u64 t, %1; cvt.u32.u64 %0, t; }" : "=r"(a) : "l"(p));
    return a;
}
__device__ __forceinline__ void cp16(uint32_t s, const void* g) {
    asm volatile("{ .reg .u64 gg; cvta.to.global.u64 gg, %1;"
                 "  cp.async.cg.shared.global [%0], [gg], 16; }"
                 :: "r"(s), "l"(g));
}
#define CP_COMMIT() asm volatile("cp.async.commit_group;" ::: "memory")
#define CP_WAIT1()  asm volatile("cp.async.wait_group 1;"  ::: "memory")

__device__ __forceinline__ void ldsm4(uint32_t& r0, uint32_t& r1, uint32_t& r2, uint32_t& r3,
                                      uint32_t addr) {
    asm volatile("ldmatrix.sync.aligned.m8n8.x4.shared.b16 {%0,%1,%2,%3}, [%4];"
                 : "=r"(r0), "=r"(r1), "=r"(r2), "=r"(r3) : "r"(addr));
}

// fp16 MMA: D(f32) += A(f16) * B(f16), m16n8k16
__device__ __forceinline__ void mma16(float* d, const uint32_t* a, const uint32_t* b) {
    asm volatile(
        "mma.sync.aligned.m16n8k16.row.col.f32.f16.f16.f32 "
        "{%0,%1,%2,%3}, {%4,%5,%6,%7}, {%8,%9}, {%0,%1,%2,%3};"
        : "+f"(d[0]), "+f"(d[1]), "+f"(d[2]), "+f"(d[3])
        : "r"(a[0]), "r"(a[1]), "r"(a[2]), "r"(a[3]), "r"(b[0]), "r"(b[1]));
}

// ---------------------------------------------------------------------------
// mainloop (512 threads), fp16, BK=32: acc[MT][4][4] += A[MT*64,K] * B[128,K]^T
// 16 warps = 4(m) x 4(n); warp tile (MT*16)x32; m16n8k16; ldmatrix frags;
// 2-stage cp.async, two syncs per chunk (R10 structure — best known).
// ---------------------------------------------------------------------------
template <int MT>
__device__ __forceinline__ void gemm_mainloop(
    float (*acc)[4][4], char* smem,
    const __half* __restrict__ Ag, int lda, int arow0,
    const __half* __restrict__ Bg, int ldb, int brow0,
    int kbeg, int kend)
{
    constexpr int AROWS  = MT * 64;
    constexpr int ABUF   = AROWS * PADH * 2;
    constexpr int STAGEB = ABUF + BBUF;

    const int tid  = threadIdx.x;
    const int wid  = tid >> 5, lane = tid & 31;
    const int wm   = (wid & 3) * (MT * 16);
    const int wn   = (wid >> 2) * 32;
    const uint32_t sA = smem_u32(smem);
    const int nch  = (kend - kbeg) >> 5;

    const uint32_t aoff = ((wm + (lane & 15)) * PADH + (lane >> 4) * 8) * 2;
    const uint32_t boff = ABUF +
        ((wn + (lane & 7) + ((lane >> 4) & 1) * 8) * PADH + ((lane >> 3) & 1) * 8) * 2;

    const int ach = (MT == 4) ? 2 : 1;
    const int alm = (MT == 4) ? (tid >> 1) : (tid >> 2);
    const int alq = (MT == 4) ? ((tid & 1) * 2) : (tid & 3);
    const int blm = tid >> 2;
    const int blq = tid & 3;

#define ISSUE_CHUNK(stg, k0) do {                                              \
    uint32_t _st = sA + (stg) * STAGEB;                                        \
    _Pragma("unroll")                                                          \
    for (int q = 0; q < ach; q++)                                              \
        cp16(_st + (alm * PADH + (alq + q) * 8) * 2,                           \
             Ag + (size_t)(arow0 + alm) * lda + (k0) + (alq + q) * 8);         \
    cp16(_st + ABUF + (blm * PADH + blq * 8) * 2,                              \
         Bg + (size_t)(brow0 + blm) * ldb + (k0) + blq * 8);                   \
} while (0)

    ISSUE_CHUNK(0, kbeg);
    CP_COMMIT();
    if (nch > 1) ISSUE_CHUNK(1, kbeg + 32);
    CP_COMMIT();

    for (int c = 0; c < nch; c++) {
        CP_WAIT1();
        __syncthreads();
        const uint32_t sb = sA + (c & 1) * STAGEB;
#pragma unroll
        for (int ks = 0; ks < 2; ks++) {
            uint32_t af[MT][4], bf[4][2];
#pragma unroll
            for (int mt = 0; mt < MT; mt++)
                ldsm4(af[mt][0], af[mt][1], af[mt][2], af[mt][3],
                      sb + aoff + mt * (16 * PADH * 2) + ks * 32);
            ldsm4(bf[0][0], bf[0][1], bf[1][0], bf[1][1], sb + boff + ks * 32);
            ldsm4(bf[2][0], bf[2][1], bf[3][0], bf[3][1],
                  sb + boff + 16 * PADH * 2 + ks * 32);
#pragma unroll
            for (int mt = 0; mt < MT; mt++)
#pragma unroll
                for (int nt = 0; nt < 4; nt++)
                    mma16(acc[mt][nt], af[mt], bf[nt]);
        }
        __syncthreads();
        if (c + 2 < nch) ISSUE_CHUNK(c & 1, kbeg + (c + 2) * 32);
        CP_COMMIT();
    }
#undef ISSUE_CHUNK
}

#define GEMM_THREAD_COORDS(MT)                                   \
    const int tid = threadIdx.x;                                 \
    const int wid = tid >> 5, lane = tid & 31;                   \
    const int wm = (wid & 3) * ((MT) * 16), wn = (wid >> 2) * 32;\
    const int r = lane >> 2, cc = lane & 3;

#define ZERO_ACC(acc, MT)                                        \
    float acc[MT][4][4];                                         \
    _Pragma("unroll")                                            \
    for (int i = 0; i < MT; i++)                                 \
        _Pragma("unroll")                                        \
        for (int j = 0; j < 4; j++)                              \
            _Pragma("unroll")                                    \
            for (int q = 0; q < 4; q++) acc[i][j][q] = 0.f;

// ---------------------------------------------------------------------------
// QK projections: z=0: Q = x@Wq' + bq ; z=1: K
// grid (128,1,2): bi=b>>3 (16 m-tiles of 256), bj=b&7 (8 n-tiles of 128)
// ---------------------------------------------------------------------------
__global__ __launch_bounds__(512, 1) void gemm_qk_kernel(
    const float* __restrict__ bq, const float* __restrict__ bk)
{
    const int z = blockIdx.z;
    extern __shared__ char smem[];
    const int b = blockIdx.x;
    const int row0 = (b >> 3) * 256;
    const int col0 = (b & 7) * 128;

    ZERO_ACC(acc, 4);

    const __half* Bg  = (z == 0) ? g_wt : g_wt + DIM * DIM;
    const float* bias = (z == 0) ? bq : bk;

    gemm_mainloop<4>(acc, smem, g_x, DIM, row0, Bg, DIM, col0, 0, DIM);

    GEMM_THREAD_COORDS(4);
    __half* dst = (z == 0) ? g_q : g_k;

#pragma unroll
    for (int mt = 0; mt < 4; mt++)
#pragma unroll
        for (int h = 0; h < 2; h++) {
            int m = row0 + wm + mt * 16 + r + 8 * h;
#pragma unroll
            for (int nt = 0; nt < 4; nt++) {
                int n = col0 + wn + nt * 8 + 2 * cc;
                float v0 = acc[mt][nt][2 * h + 0] + bias[n];
                float v1 = acc[mt][nt][2 * h + 1] + bias[n + 1];
                *(__half2*)&dst[(size_t)m * DIM + n] = __floats2half2_rn(v0, v1);
            }
        }
}

// ---------------------------------------------------------------------------
// V^T = Wvt @ x^T + bv(row).  grid (128): bi=b>>5 (4 m-tiles over DIM),
// bj=b&31 (32 n-tiles of 128 over SEQ)
// ---------------------------------------------------------------------------
__global__ __launch_bounds__(512, 1) void gemm_v_kernel(const float* __restrict__ bv)
{
    extern __shared__ char smem[];
    const int b = blockIdx.x;
    const int row0 = (b >> 5) * 256;
    const int col0 = (b & 31) * 128;

    ZERO_ACC(acc, 4);
    gemm_mainloop<4>(acc, smem, g_wt + 2 * DIM * DIM, DIM, row0, g_x, DIM, col0, 0, DIM);

    GEMM_THREAD_COORDS(4);
#pragma unroll
    for (int mt = 0; mt < 4; mt++)
#pragma unroll
        for (int h = 0; h < 2; h++) {
            int m = row0 + wm + mt * 16 + r + 8 * h;
            float brow = bv[m];
#pragma unroll
            for (int nt = 0; nt < 4; nt++) {
                int n = col0 + wn + nt * 8 + 2 * cc;
                float v0 = acc[mt][nt][2 * h + 0] + brow;
                float v1 = acc[mt][nt][2 * h + 1] + brow;
                *(__half2*)&g_vt[(size_t)m * SEQ + n] = __floats2half2_rn(v0, v1);
            }
        }
}

// ---------------------------------------------------------------------------
// scores: S = SCALE * Q K^T (fp16 out), tiles 256x128; kept iff bj >= 2*bi
// ---------------------------------------------------------------------------
__global__ __launch_bounds__(512, 1) void gemm_scores_kernel()
{
    int bi = 0, rem = blockIdx.x;
    while (rem >= 32 - 2 * bi) { rem -= 32 - 2 * bi; bi++; }
    const int bj = 2 * bi + rem;

    extern __shared__ char smem[];
    const int row0 = bi * 256, col0 = bj * 128;

    ZERO_ACC(acc, 4);
    gemm_mainloop<4>(acc, smem, g_q, DIM, row0, g_k, DIM, col0, 0, DIM);

    GEMM_THREAD_COORDS(4);
#pragma unroll
    for (int mt = 0; mt < 4; mt++)
#pragma unroll
        for (int h = 0; h < 2; h++) {
            int m = row0 + wm + mt * 16 + r + 8 * h;
#pragma unroll
            for (int nt = 0; nt < 4; nt++) {
                int n = col0 + wn + nt * 8 + 2 * cc;
                *(__half2*)&g_s[(size_t)m * SEQ + n] =
                    __floats2half2_rn(acc[mt][nt][2 * h] * SCALE,
                                      acc[mt][nt][2 * h + 1] * SCALE);
            }
        }
}

// ---------------------------------------------------------------------------
// softmax over j >= i (half8 vectorized); zero strip to 256-aligned tile base
// ---------------------------------------------------------------------------
__global__ __launch_bounds__(256) void softmax_kernel()
{
    const int i = blockIdx.x;
    const int t = threadIdx.x;
    const uint4* row8 = (const uint4*)(g_s + (size_t)i * SEQ);
    const int rowstart = i & ~255;

    float v[16];
    float m = -INFINITY;
#pragma unroll
    for (int c = 0; c < 2; c++) {
        const int q8 = t + (c << 8);        // half8 index 0..511
        const int j = q8 << 3;
        if (j + 7 >= i) {
            uint4 u = row8[q8];
            const uint32_t uu[4] = {u.x, u.y, u.z, u.w};
#pragma unroll
            for (int e = 0; e < 4; e++) {
                float2 f = __half22float2(*(const __half2*)&uu[e]);
                v[c * 8 + 2 * e + 0] = (j + 2 * e + 0 >= i) ? f.x : -INFINITY;
                v[c * 8 + 2 * e + 1] = (j + 2 * e + 1 >= i) ? f.y : -INFINITY;
            }
        } else {
#pragma unroll
            for (int e = 0; e < 8; e++) v[c * 8 + e] = -INFINITY;
        }
#pragma unroll
        for (int e = 0; e < 8; e++) m = fmaxf(m, v[c * 8 + e]);
    }

    __shared__ float red[8];
#pragma unroll
    for (int o = 16; o > 0; o >>= 1) m = fmaxf(m, __shfl_xor_sync(0xffffffffu, m, o));
    if ((t & 31) == 0) red[t >> 5] = m;
    __syncthreads();
    float mm = red[0];
#pragma unroll
    for (int w = 1; w < 8; w++) mm = fmaxf(mm, red[w]);
    __syncthreads();

    float sum = 0.f;
#pragma unroll
    for (int e = 0; e < 16; e++) {
        float x = (v[e] > -INFINITY) ? __expf(v[e] - mm) : 0.f;
        v[e] = x;
        sum += x;
    }
#pragma unroll
    for (int o = 16; o > 0; o >>= 1) sum += __shfl_xor_sync(0xffffffffu, sum, o);
    if ((t & 31) == 0) red[t >> 5] = sum;
    __syncthreads();
    float tot = 0.f;
#pragma unroll
    for (int w = 0; w < 8; w++) tot += red[w];
    const float inv = 1.0f / tot;

    __half* p = g_p + (size_t)i * SEQ;
#pragma unroll
    for (int c = 0; c < 2; c++) {
        const int q8 = t + (c << 8);
        const int j = q8 << 3;
        if (j >= rowstart) {
            uint4 u;
            uint32_t* uu = (uint32_t*)&u;
#pragma unroll
            for (int e = 0; e < 4; e++) {
                __half2 h = __floats2half2_rn(v[c * 8 + 2 * e] * inv,
                                              v[c * 8 + 2 * e + 1] * inv);
                uu[e] = *(uint32_t*)&h;
            }
            *(uint4*)&p[j] = u;
        }
    }
}

// ---------------------------------------------------------------------------
// PV: read = P @ V ; tiles 256x128 (MT=4); k starts at the diagonal 256-tile.
// grid (8, 16): row0 = y*256, col0 = x*128
// ---------------------------------------------------------------------------
__global__ __launch_bounds__(512, 1) void gemm_pv_kernel(float* __restrict__ out)
{
    extern __shared__ char smem[];
    const int row0 = blockIdx.y * 256, col0 = blockIdx.x * 128;

    ZERO_ACC(acc, 4);
    gemm_mainloop<4>(acc, smem, g_p, SEQ, row0, g_vt, SEQ, col0, row0, SEQ);

    GEMM_THREAD_COORDS(4);
#pragma unroll
    for (int mt = 0; mt < 4; mt++)
#pragma unroll
        for (int h = 0; h < 2; h++) {
            int m = row0 + wm + mt * 16 + r + 8 * h;
#pragma unroll
            for (int nt = 0; nt < 4; nt++) {
                int n = col0 + wn + nt * 8 + 2 * cc;
                float2 w = make_float2(acc[mt][nt][2 * h], acc[mt][nt][2 * h + 1]);
                *(float2*)&out[(size_t)m * OUTD + DIM + n] = w;
            }
        }
}

// ---------------------------------------------------------------------------
// conversions
// ---------------------------------------------------------------------------
__global__ __launch_bounds__(256) void conv_x_kernel(const float* __restrict__ x,
                                                     float* __restrict__ out)
{
    int idx = blockIdx.x * 256 + threadIdx.x;   // float4 index
    int r = idx >> 8;
    int c = (idx & 255) * 4;
    float4 v = *(const float4*)&x[(size_t)r * DIM + c];
    *(float4*)&out[(size_t)r * OUTD + c] = v;   // out[:, 0:1024] = x
    __half2 h0 = __floats2half2_rn(v.x, v.y);
    __half2 h1 = __floats2half2_rn(v.z, v.w);
    *(__half2*)&g_x[(size_t)r * DIM + c]     = h0;
    *(__half2*)&g_x[(size_t)r * DIM + c + 2] = h1;
}

// transpose + fp16-convert W [k][n] -> Wt [n][k] (slot z: 0=Q, 1=K, 2=V)
__global__ __launch_bounds__(256) void conv_w_kernel(const float* __restrict__ Wq,
                                                     const float* __restrict__ Wk,
                                                     const float* __restrict__ Wv)
{
    __shared__ float t[32][33];
    const int z = blockIdx.z;
    const float* W = (z == 0) ? Wq : (z == 1) ? Wk : Wv;
    const int n0 = blockIdx.x * 32, k0 = blockIdx.y * 32;
    const int tx = threadIdx.x & 31, ty = threadIdx.x >> 5;
#pragma unroll
    for (int i = 0; i < 4; i++) {
        int k = ty + i * 8;
        t[k][tx] = W[(size_t)(k0 + k) * DIM + n0 + tx];
    }
    __syncthreads();
    __half* T = g_wt + (size_t)z * DIM * DIM;
#pragma unroll
    for (int i = 0; i < 4; i++) {
        int n = ty + i * 8;
        T[(size_t)(n0 + n) * DIM + k0 + tx] = __float2half(t[tx][n]);
    }
}

// ---------------------------------------------------------------------------
extern "C" void kernel_launch(void* const* d_in, const int* in_sizes, int n_in,
                              void* d_out, int out_size)
{
    const float* x  = (const float*)d_in[0];
    const float* Wk = (const float*)d_in[1];
    const float* bk = (const float*)d_in[2];
    const float* Wq = (const float*)d_in[3];
    const float* bq = (const float*)d_in[4];
    const float* Wv = (const float*)d_in[5];
    const float* bv = (const float*)d_in[6];
    float* out = (float*)d_out;

    const int SM4 = 2 * (256 * PADH * 2 + BBUF);   // 61440

    // one-time resource creation (first, non-captured call)
    static cudaStream_t s2 = nullptr;
    static cudaEvent_t ev1 = nullptr, ev2 = nullptr;
    if (!s2) {
        cudaStreamCreate(&s2);
        cudaEventCreateWithFlags(&ev1, cudaEventDisableTiming);
        cudaEventCreateWithFlags(&ev2, cudaEventDisableTiming);
        cudaFuncSetAttribute(gemm_qk_kernel,     cudaFuncAttributeMaxDynamicSharedMemorySize, SM4);
        cudaFuncSetAttribute(gemm_v_kernel,      cudaFuncAttributeMaxDynamicSharedMemorySize, SM4);
        cudaFuncSetAttribute(gemm_scores_kernel, cudaFuncAttributeMaxDynamicSharedMemorySize, SM4);
        cudaFuncSetAttribute(gemm_pv_kernel,     cudaFuncAttributeMaxDynamicSharedMemorySize, SM4);
    }

    // stream 0 (captured legacy stream): conversions
    conv_x_kernel<<<4096, 256>>>(x, out);
    conv_w_kernel<<<dim3(32, 32, 3), 256>>>(Wq, Wk, Wv);

    // fork: V^T on s2 (independent of scores/softmax chain)
    cudaEventRecord(ev1, 0);
    cudaStreamWaitEvent(s2, ev1, 0);
    gemm_v_kernel<<<128, 512, SM4, s2>>>(bv);
    cudaEventRecord(ev2, s2);

    // main chain on stream 0
    gemm_qk_kernel<<<dim3(128, 1, 2), 512, SM4>>>(bq, bk);
    gemm_scores_kernel<<<272, 512, SM4>>>();
    softmax_kernel<<<SEQ, 256>>>();

    // join: PV needs V^T + probs
    cudaStreamWaitEvent(0, ev2, 0);
    gemm_pv_kernel<<<dim3(8, 16), 512, SM4>>>(out);
}

// round 14
// speedup vs baseline: 1.1995x; 1.1995x over previous
#include <cuda_runtime.h>
#include <cuda_fp16.h>
#include <math.h>
#include <stdint.h>

#define SEQ   4096
#define DIM   1024
#define OUTD  2048
#define SCALE 0.03125f   // 1/sqrt(1024)

#define PADH  40                        // 32 halves + 8 pad per smem row (80 B)
#define BBUF  (128 * PADH * 2)          // B tile: 10240 B

// ---------------------------------------------------------------------------
// scratch (__device__ globals; no allocations allowed)
// ---------------------------------------------------------------------------
__device__ __half g_x [(size_t)SEQ * DIM];          // x (fp16)
__device__ __half g_wt[(size_t)3 * DIM * DIM];      // W^T (Q,K,V) (fp16)
__device__ __half g_q [(size_t)SEQ * DIM];
__device__ __half g_k [(size_t)SEQ * DIM];
__device__ __half g_vt[(size_t)DIM * SEQ];          // V^T [d][s]
__device__ __half g_s [(size_t)SEQ * SEQ];          // scaled scores (fp16)
__device__ __half g_p [(size_t)SEQ * SEQ];          // probs (fp16)

// ---------------------------------------------------------------------------
// helpers
// ---------------------------------------------------------------------------
__device__ __forceinline__ uint32_t smem_u32(const void* p) {
    uint32_t a;
    asm("{ .reg .u64 t; cvta.to.shared.u64 t, %1; cvt.u32.u64 %0, t; }" : "=r"(a) : "l"(p));
    return a;
}
__device__ __forceinline__ void cp16(uint32_t s, const void* g) {
    asm volatile("{ .reg .u64 gg; cvta.to.global.u64 gg, %1;"
                 "  cp.async.cg.shared.global [%0], [gg], 16; }"
                 :: "r"(s), "l"(g));
}
#define CP_COMMIT() asm volatile("cp.async.commit_group;" ::: "memory")
#define CP_WAIT1()  asm volatile("cp.async.wait_group 1;"  ::: "memory")

__device__ __forceinline__ void ldsm4(uint32_t& r0, uint32_t& r1, uint32_t& r2, uint32_t& r3,
                                      uint32_t addr) {
    asm volatile("ldmatrix.sync.aligned.m8n8.x4.shared.b16 {%0,%1,%2,%3}, [%4];"
                 : "=r"(r0), "=r"(r1), "=r"(r2), "=r"(r3) : "r"(addr));
}

// fp16 MMA: D(f32) += A(f16) * B(f16), m16n8k16
__device__ __forceinline__ void mma16(float* d, const uint32_t* a, const uint32_t* b) {
    asm volatile(
        "mma.sync.aligned.m16n8k16.row.col.f32.f16.f16.f32 "
        "{%0,%1,%2,%3}, {%4,%5,%6,%7}, {%8,%9}, {%0,%1,%2,%3};"
        : "+f"(d[0]), "+f"(d[1]), "+f"(d[2]), "+f"(d[3])
        : "r"(a[0]), "r"(a[1]), "r"(a[2]), "r"(a[3]), "r"(b[0]), "r"(b[1]));
}

// ---------------------------------------------------------------------------
// mainloop (512 threads), fp16, BK=32: acc[MT][4][4] += A[MT*64,K] * B[128,K]^T
// 16 warps = 4(m) x 4(n); warp tile (MT*16)x32; m16n8k16; ldmatrix frags;
// 2-stage cp.async, two syncs per chunk (R10/R12 structure — best known).
// ---------------------------------------------------------------------------
template <int MT>
__device__ __forceinline__ void gemm_mainloop(
    float (*acc)[4][4], char* smem,
    const __half* __restrict__ Ag, int lda, int arow0,
    const __half* __restrict__ Bg, int ldb, int brow0,
    int kbeg, int kend)
{
    constexpr int AROWS  = MT * 64;
    constexpr int ABUF   = AROWS * PADH * 2;
    constexpr int STAGEB = ABUF + BBUF;

    const int tid  = threadIdx.x;
    const int wid  = tid >> 5, lane = tid & 31;
    const int wm   = (wid & 3) * (MT * 16);
    const int wn   = (wid >> 2) * 32;
    const uint32_t sA = smem_u32(smem);
    const int nch  = (kend - kbeg) >> 5;

    const uint32_t aoff = ((wm + (lane & 15)) * PADH + (lane >> 4) * 8) * 2;
    const uint32_t boff = ABUF +
        ((wn + (lane & 7) + ((lane >> 4) & 1) * 8) * PADH + ((lane >> 3) & 1) * 8) * 2;

    const int ach = (MT == 4) ? 2 : 1;
    const int alm = (MT == 4) ? (tid >> 1) : (tid >> 2);
    const int alq = (MT == 4) ? ((tid & 1) * 2) : (tid & 3);
    const int blm = tid >> 2;
    const int blq = tid & 3;

#define ISSUE_CHUNK(stg, k0) do {                                              \
    uint32_t _st = sA + (stg) * STAGEB;                                        \
    _Pragma("unroll")                                                          \
    for (int q = 0; q < ach; q++)                                              \
        cp16(_st + (alm * PADH + (alq + q) * 8) * 2,                           \
             Ag + (size_t)(arow0 + alm) * lda + (k0) + (alq + q) * 8);         \
    cp16(_st + ABUF + (blm * PADH + blq * 8) * 2,                              \
         Bg + (size_t)(brow0 + blm) * ldb + (k0) + blq * 8);                   \
} while (0)

    ISSUE_CHUNK(0, kbeg);
    CP_COMMIT();
    if (nch > 1) ISSUE_CHUNK(1, kbeg + 32);
    CP_COMMIT();

    for (int c = 0; c < nch; c++) {
        CP_WAIT1();
        __syncthreads();
        const uint32_t sb = sA + (c & 1) * STAGEB;
#pragma unroll
        for (int ks = 0; ks < 2; ks++) {
            uint32_t af[MT][4], bf[4][2];
#pragma unroll
            for (int mt = 0; mt < MT; mt++)
                ldsm4(af[mt][0], af[mt][1], af[mt][2], af[mt][3],
                      sb + aoff + mt * (16 * PADH * 2) + ks * 32);
            ldsm4(bf[0][0], bf[0][1], bf[1][0], bf[1][1], sb + boff + ks * 32);
            ldsm4(bf[2][0], bf[2][1], bf[3][0], bf[3][1],
                  sb + boff + 16 * PADH * 2 + ks * 32);
#pragma unroll
            for (int mt = 0; mt < MT; mt++)
#pragma unroll
                for (int nt = 0; nt < 4; nt++)
                    mma16(acc[mt][nt], af[mt], bf[nt]);
        }
        __syncthreads();
        if (c + 2 < nch) ISSUE_CHUNK(c & 1, kbeg + (c + 2) * 32);
        CP_COMMIT();
    }
#undef ISSUE_CHUNK
}

#define GEMM_THREAD_COORDS(MT)                                   \
    const int tid = threadIdx.x;                                 \
    const int wid = tid >> 5, lane = tid & 31;                   \
    const int wm = (wid & 3) * ((MT) * 16), wn = (wid >> 2) * 32;\
    const int r = lane >> 2, cc = lane & 3;

#define ZERO_ACC(acc, MT)                                        \
    float acc[MT][4][4];                                         \
    _Pragma("unroll")                                            \
    for (int i = 0; i < MT; i++)                                 \
        _Pragma("unroll")                                        \
        for (int j = 0; j < 4; j++)                              \
            _Pragma("unroll")                                    \
            for (int q = 0; q < 4; q++) acc[i][j][q] = 0.f;

// ---------------------------------------------------------------------------
// QK projections: z=0: Q = x@Wq' + bq ; z=1: K
// grid (128,1,2): bi=b>>3 (16 m-tiles of 256), bj=b&7 (8 n-tiles of 128)
// ---------------------------------------------------------------------------
__global__ __launch_bounds__(512, 1) void gemm_qk_kernel(
    const float* __restrict__ bq, const float* __restrict__ bk)
{
    const int z = blockIdx.z;
    extern __shared__ char smem[];
    const int b = blockIdx.x;
    const int row0 = (b >> 3) * 256;
    const int col0 = (b & 7) * 128;

    ZERO_ACC(acc, 4);

    const __half* Bg  = (z == 0) ? g_wt : g_wt + DIM * DIM;
    const float* bias = (z == 0) ? bq : bk;

    gemm_mainloop<4>(acc, smem, g_x, DIM, row0, Bg, DIM, col0, 0, DIM);

    GEMM_THREAD_COORDS(4);
    __half* dst = (z == 0) ? g_q : g_k;

#pragma unroll
    for (int mt = 0; mt < 4; mt++)
#pragma unroll
        for (int h = 0; h < 2; h++) {
            int m = row0 + wm + mt * 16 + r + 8 * h;
#pragma unroll
            for (int nt = 0; nt < 4; nt++) {
                int n = col0 + wn + nt * 8 + 2 * cc;
                float v0 = acc[mt][nt][2 * h + 0] + bias[n];
                float v1 = acc[mt][nt][2 * h + 1] + bias[n + 1];
                *(__half2*)&dst[(size_t)m * DIM + n] = __floats2half2_rn(v0, v1);
            }
        }
}

// ---------------------------------------------------------------------------
// V^T = Wvt @ x^T + bv(row).  grid (128): bi=b>>5 (4 m-tiles over DIM),
// bj=b&31 (32 n-tiles of 128 over SEQ)
// ---------------------------------------------------------------------------
__global__ __launch_bounds__(512, 1) void gemm_v_kernel(const float* __restrict__ bv)
{
    extern __shared__ char smem[];
    const int b = blockIdx.x;
    const int row0 = (b >> 5) * 256;
    const int col0 = (b & 31) * 128;

    ZERO_ACC(acc, 4);
    gemm_mainloop<4>(acc, smem, g_wt + 2 * DIM * DIM, DIM, row0, g_x, DIM, col0, 0, DIM);

    GEMM_THREAD_COORDS(4);
#pragma unroll
    for (int mt = 0; mt < 4; mt++)
#pragma unroll
        for (int h = 0; h < 2; h++) {
            int m = row0 + wm + mt * 16 + r + 8 * h;
            float brow = bv[m];
#pragma unroll
            for (int nt = 0; nt < 4; nt++) {
                int n = col0 + wn + nt * 8 + 2 * cc;
                float v0 = acc[mt][nt][2 * h + 0] + brow;
                float v1 = acc[mt][nt][2 * h + 1] + brow;
                *(__half2*)&g_vt[(size_t)m * SEQ + n] = __floats2half2_rn(v0, v1);
            }
        }
}

// ---------------------------------------------------------------------------
// scores: S = SCALE * Q K^T (fp16 out), tiles 256x128; kept iff bj >= 2*bi
// ---------------------------------------------------------------------------
__global__ __launch_bounds__(512, 1) void gemm_scores_kernel()
{
    int bi = 0, rem = blockIdx.x;
    while (rem >= 32 - 2 * bi) { rem -= 32 - 2 * bi; bi++; }
    const int bj = 2 * bi + rem;

    extern __shared__ char smem[];
    const int row0 = bi * 256, col0 = bj * 128;

    ZERO_ACC(acc, 4);
    gemm_mainloop<4>(acc, smem, g_q, DIM, row0, g_k, DIM, col0, 0, DIM);

    GEMM_THREAD_COORDS(4);
#pragma unroll
    for (int mt = 0; mt < 4; mt++)
#pragma unroll
        for (int h = 0; h < 2; h++) {
            int m = row0 + wm + mt * 16 + r + 8 * h;
#pragma unroll
            for (int nt = 0; nt < 4; nt++) {
                int n = col0 + wn + nt * 8 + 2 * cc;
                *(__half2*)&g_s[(size_t)m * SEQ + n] =
                    __floats2half2_rn(acc[mt][nt][2 * h] * SCALE,
                                      acc[mt][nt][2 * h + 1] * SCALE);
            }
        }
}

// ---------------------------------------------------------------------------
// softmax over j >= i (half8 vectorized); zero strip to 128-aligned tile base
// ---------------------------------------------------------------------------
__global__ __launch_bounds__(256) void softmax_kernel()
{
    const int i = blockIdx.x;
    const int t = threadIdx.x;
    const uint4* row8 = (const uint4*)(g_s + (size_t)i * SEQ);
    const int rowstart = i & ~127;

    float v[16];
    float m = -INFINITY;
#pragma unroll
    for (int c = 0; c < 2; c++) {
        const int q8 = t + (c << 8);        // half8 index 0..511
        const int j = q8 << 3;
        if (j + 7 >= i) {
            uint4 u = row8[q8];
            const uint32_t uu[4] = {u.x, u.y, u.z, u.w};
#pragma unroll
            for (int e = 0; e < 4; e++) {
                float2 f = __half22float2(*(const __half2*)&uu[e]);
                v[c * 8 + 2 * e + 0] = (j + 2 * e + 0 >= i) ? f.x : -INFINITY;
                v[c * 8 + 2 * e + 1] = (j + 2 * e + 1 >= i) ? f.y : -INFINITY;
            }
        } else {
#pragma unroll
            for (int e = 0; e < 8; e++) v[c * 8 + e] = -INFINITY;
        }
#pragma unroll
        for (int e = 0; e < 8; e++) m = fmaxf(m, v[c * 8 + e]);
    }

    __shared__ float red[8];
#pragma unroll
    for (int o = 16; o > 0; o >>= 1) m = fmaxf(m, __shfl_xor_sync(0xffffffffu, m, o));
    if ((t & 31) == 0) red[t >> 5] = m;
    __syncthreads();
    float mm = red[0];
#pragma unroll
    for (int w = 1; w < 8; w++) mm = fmaxf(mm, red[w]);
    __syncthreads();

    float sum = 0.f;
#pragma unroll
    for (int e = 0; e < 16; e++) {
        float x = (v[e] > -INFINITY) ? __expf(v[e] - mm) : 0.f;
        v[e] = x;
        sum += x;
    }
#pragma unroll
    for (int o = 16; o > 0; o >>= 1) sum += __shfl_xor_sync(0xffffffffu, sum, o);
    if ((t & 31) == 0) red[t >> 5] = sum;
    __syncthreads();
    float tot = 0.f;
#pragma unroll
    for (int w = 0; w < 8; w++) tot += red[w];
    const float inv = 1.0f / tot;

    __half* p = g_p + (size_t)i * SEQ;
#pragma unroll
    for (int c = 0; c < 2; c++) {
        const int q8 = t + (c << 8);
        const int j = q8 << 3;
        if (j >= rowstart) {
            uint4 u;
            uint32_t* uu = (uint32_t*)&u;
#pragma unroll
            for (int e = 0; e < 4; e++) {
                __half2 h = __floats2half2_rn(v[c * 8 + 2 * e] * inv,
                                              v[c * 8 + 2 * e + 1] * inv);
                uu[e] = *(uint32_t*)&h;
            }
            *(uint4*)&p[j] = u;
        }
    }
}

// ---------------------------------------------------------------------------
// PV: read = P @ V ; tiles 128x128 (MT=2); k starts at the diagonal 128-tile.
// grid (8, 32): row0 = y*128, col0 = x*128
// ---------------------------------------------------------------------------
__global__ __launch_bounds__(512, 1) void gemm_pv_kernel(float* __restrict__ out)
{
    extern __shared__ char smem[];
    const int row0 = blockIdx.y * 128, col0 = blockIdx.x * 128;

    ZERO_ACC(acc, 2);
    gemm_mainloop<2>(acc, smem, g_p, SEQ, row0, g_vt, SEQ, col0, row0, SEQ);

    GEMM_THREAD_COORDS(2);
#pragma unroll
    for (int mt = 0; mt < 2; mt++)
#pragma unroll
        for (int h = 0; h < 2; h++) {
            int m = row0 + wm + mt * 16 + r + 8 * h;
#pragma unroll
            for (int nt = 0; nt < 4; nt++) {
                int n = col0 + wn + nt * 8 + 2 * cc;
                float2 w = make_float2(acc[mt][nt][2 * h], acc[mt][nt][2 * h + 1]);
                *(float2*)&out[(size_t)m * OUTD + DIM + n] = w;
            }
        }
}

// ---------------------------------------------------------------------------
// conversions
// ---------------------------------------------------------------------------
__global__ __launch_bounds__(256) void conv_x_kernel(const float* __restrict__ x,
                                                     float* __restrict__ out)
{
    int idx = blockIdx.x * 256 + threadIdx.x;   // float4 index
    int r = idx >> 8;
    int c = (idx & 255) * 4;
    float4 v = *(const float4*)&x[(size_t)r * DIM + c];
    *(float4*)&out[(size_t)r * OUTD + c] = v;   // out[:, 0:1024] = x
    __half2 h0 = __floats2half2_rn(v.x, v.y);
    __half2 h1 = __floats2half2_rn(v.z, v.w);
    *(__half2*)&g_x[(size_t)r * DIM + c]     = h0;
    *(__half2*)&g_x[(size_t)r * DIM + c + 2] = h1;
}

// transpose + fp16-convert W [k][n] -> Wt [n][k] (slot z: 0=Q, 1=K, 2=V)
__global__ __launch_bounds__(256) void conv_w_kernel(const float* __restrict__ Wq,
                                                     const float* __restrict__ Wk,
                                                     const float* __restrict__ Wv)
{
    __shared__ float t[32][33];
    const int z = blockIdx.z;
    const float* W = (z == 0) ? Wq : (z == 1) ? Wk : Wv;
    const int n0 = blockIdx.x * 32, k0 = blockIdx.y * 32;
    const int tx = threadIdx.x & 31, ty = threadIdx.x >> 5;
#pragma unroll
    for (int i = 0; i < 4; i++) {
        int k = ty + i * 8;
        t[k][tx] = W[(size_t)(k0 + k) * DIM + n0 + tx];
    }
    __syncthreads();
    __half* T = g_wt + (size_t)z * DIM * DIM;
#pragma unroll
    for (int i = 0; i < 4; i++) {
        int n = ty + i * 8;
        T[(size_t)(n0 + n) * DIM + k0 + tx] = __float2half(t[tx][n]);
    }
}

// ---------------------------------------------------------------------------
extern "C" void kernel_launch(void* const* d_in, const int* in_sizes, int n_in,
                              void* d_out, int out_size)
{
    const float* x  = (const float*)d_in[0];
    const float* Wk = (const float*)d_in[1];
    const float* bk = (const float*)d_in[2];
    const float* Wq = (const float*)d_in[3];
    const float* bq = (const float*)d_in[4];
    const float* Wv = (const float*)d_in[5];
    const float* bv = (const float*)d_in[6];
    float* out = (float*)d_out;

    const int SM4 = 2 * (256 * PADH * 2 + BBUF);   // 61440
    const int SM2 = 2 * (128 * PADH * 2 + BBUF);   // 40960

    // one-time resource creation (first, non-captured call)
    static cudaStream_t s2 = nullptr;
    static cudaEvent_t ev1 = nullptr, ev2 = nullptr;
    if (!s2) {
        cudaStreamCreate(&s2);
        cudaEventCreateWithFlags(&ev1, cudaEventDisableTiming);
        cudaEventCreateWithFlags(&ev2, cudaEventDisableTiming);
        cudaFuncSetAttribute(gemm_qk_kernel,     cudaFuncAttributeMaxDynamicSharedMemorySize, SM4);
        cudaFuncSetAttribute(gemm_v_kernel,      cudaFuncAttributeMaxDynamicSharedMemorySize, SM4);
        cudaFuncSetAttribute(gemm_scores_kernel, cudaFuncAttributeMaxDynamicSharedMemorySize, SM4);
        cudaFuncSetAttribute(gemm_pv_kernel,     cudaFuncAttributeMaxDynamicSharedMemorySize, SM2);
    }

    // stream 0 (captured legacy stream): conversions
    conv_x_kernel<<<4096, 256>>>(x, out);
    conv_w_kernel<<<dim3(32, 32, 3), 256>>>(Wq, Wk, Wv);

    // fork: V^T on s2 (independent of scores/softmax chain)
    cudaEventRecord(ev1, 0);
    cudaStreamWaitEvent(s2, ev1, 0);
    gemm_v_kernel<<<128, 512, SM4, s2>>>(bv);
    cudaEventRecord(ev2, s2);

    // main chain on stream 0
    gemm_qk_kernel<<<dim3(128, 1, 2), 512, SM4>>>(bq, bk);
    gemm_scores_kernel<<<272, 512, SM4>>>();
    softmax_kernel<<<SEQ, 256>>>();

    // join: PV needs V^T + probs
    cudaStreamWaitEvent(0, ev2, 0);
    gemm_pv_kernel<<<dim3(8, 32), 512, SM2>>>(out);
}